// round 1
// baseline (speedup 1.0000x reference)
#include <cuda_runtime.h>

#define FULLMASK 0xffffffffu
typedef unsigned long long u64;

// ---- packed f32x2 helpers (Blackwell FFMA2 path: 2x fp32 FMA throughput) ----
__device__ __forceinline__ u64 pk2(float lo, float hi) {
    u64 r;
    asm("mov.b64 %0, {%1, %2};" : "=l"(r)
        : "r"(__float_as_uint(lo)), "r"(__float_as_uint(hi)));
    return r;
}
__device__ __forceinline__ float2 upk2(u64 v) {
    unsigned lo, hi;
    asm("mov.b64 {%0, %1}, %2;" : "=r"(lo), "=r"(hi) : "l"(v));
    float2 f; f.x = __uint_as_float(lo); f.y = __uint_as_float(hi);
    return f;
}
__device__ __forceinline__ u64 fma2(u64 a, u64 b, u64 c) {
    u64 d;
    asm("fma.rn.f32x2 %0, %1, %2, %3;" : "=l"(d) : "l"(a), "l"(b), "l"(c));
    return d;
}
__device__ __forceinline__ u64 mul2(u64 a, u64 b) {
    u64 d;
    asm("mul.rn.f32x2 %0, %1, %2;" : "=l"(d) : "l"(a), "l"(b));
    return d;
}

static constexpr int Nn = 2048, Hh = 8, Dd = 64;
static constexpr int BM = 64, BN = 64;
static constexpr int STR  = 68;   // padded stride (floats) for Qs/Ks/Vs
static constexpr int PSTR = 64;   // stride for P tile

// dynamic smem layout (in floats)
static constexpr int OFF_Q  = 0;                  // Qs[d][m]  64 x STR
static constexpr int OFF_K  = OFF_Q + 64 * STR;   // Ks[d][n]  64 x STR
static constexpr int OFF_V  = OFF_K + 64 * STR;   // Vs[n][d]  64 x STR
static constexpr int OFF_P  = OFF_V + 64 * STR;   // Ps[m][n]  64 x PSTR
static constexpr int OFF_KK = OFF_P + 64 * PSTR;  // kk[n]     64
static constexpr int SMEM_FLOATS = OFF_KK + 64;
static constexpr int SMEM_BYTES  = SMEM_FLOATS * 4;

__global__ __launch_bounds__(256, 2)
void pe_dist_attn_kernel(const float* __restrict__ qg,
                         const float* __restrict__ kg,
                         const float* __restrict__ vg,
                         float* __restrict__ outg) {
    extern __shared__ float sm[];
    float* Qs  = sm + OFF_Q;
    float* Ks  = sm + OFF_K;
    float* Vs  = sm + OFF_V;
    float* Ps  = sm + OFF_P;
    float* kks = sm + OFF_KK;

    const int tid = threadIdx.x;
    const int tx = tid & 15;        // 16 col-groups
    const int ty = tid >> 4;        // 16 row-groups
    const int m0 = blockIdx.x * BM;
    const int bh = blockIdx.y;
    const int b  = bh >> 3;         // H = 8
    const int h  = bh & 7;
    const size_t base = (size_t)bh * Nn * Dd;

    // loader mapping: row = tid>>2 (0..63); d-chunk start = (tid&3)*4, strided by 16
    const int lrow = tid >> 2;
    const int lc0  = (tid & 3) * 4;

    // ---- load Q tile transposed: Qs[d][m] (once per CTA) ----
    {
        const float* g = qg + base + (size_t)(m0 + lrow) * Dd + lc0;
        #pragma unroll
        for (int i = 0; i < 4; i++) {
            float4 t4 = *(const float4*)(g + i * 16);
            int d = lc0 + i * 16;
            Qs[(d + 0) * STR + lrow] = t4.x;
            Qs[(d + 1) * STR + lrow] = t4.y;
            Qs[(d + 2) * STR + lrow] = t4.z;
            Qs[(d + 3) * STR + lrow] = t4.w;
        }
    }

    float row_max[4], row_sum[4];
    u64 o[4][2];
    #pragma unroll
    for (int r = 0; r < 4; r++) {
        row_max[r] = -1e30f; row_sum[r] = 0.f;
        o[r][0] = 0ull; o[r][1] = 0ull;   // packed (0.f, 0.f)
    }

    for (int kt = 0; kt < Nn / BN; kt++) {
        const size_t nbase = base + (size_t)kt * BN * Dd;

        // ---- load K transposed (+ kk row norms) and V natural ----
        {
            const float* gk = kg + nbase + (size_t)lrow * Dd + lc0;
            const float* gv = vg + nbase + (size_t)lrow * Dd + lc0;
            float kk = 0.f;
            #pragma unroll
            for (int i = 0; i < 4; i++) {
                float4 t4 = *(const float4*)(gk + i * 16);
                int d = lc0 + i * 16;
                kk += t4.x * t4.x + t4.y * t4.y + t4.z * t4.z + t4.w * t4.w;
                Ks[(d + 0) * STR + lrow] = t4.x;
                Ks[(d + 1) * STR + lrow] = t4.y;
                Ks[(d + 2) * STR + lrow] = t4.z;
                Ks[(d + 3) * STR + lrow] = t4.w;
                float4 v4 = *(const float4*)(gv + i * 16);
                *(float4*)(Vs + lrow * STR + d) = v4;
            }
            kk += __shfl_xor_sync(FULLMASK, kk, 1);
            kk += __shfl_xor_sync(FULLMASK, kk, 2);
            if ((tid & 3) == 0) kks[lrow] = kk;
        }
        __syncthreads();

        // ---- S tile: Q . K^T  (4 rows x 2 f32x2 pairs per thread) ----
        u64 acc[4][2];
        #pragma unroll
        for (int r = 0; r < 4; r++) { acc[r][0] = 0ull; acc[r][1] = 0ull; }
        #pragma unroll 16
        for (int d = 0; d < Dd; d++) {
            float4 q4 = *(const float4*)(Qs + d * STR + ty * 4);  // broadcast (2 addrs/warp)
            float4 k4 = *(const float4*)(Ks + d * STR + tx * 4);  // conflict-free
            u64 kp0 = pk2(k4.x, k4.y);
            u64 kp1 = pk2(k4.z, k4.w);
            u64 qr;
            qr = pk2(q4.x, q4.x); acc[0][0] = fma2(qr, kp0, acc[0][0]); acc[0][1] = fma2(qr, kp1, acc[0][1]);
            qr = pk2(q4.y, q4.y); acc[1][0] = fma2(qr, kp0, acc[1][0]); acc[1][1] = fma2(qr, kp1, acc[1][1]);
            qr = pk2(q4.z, q4.z); acc[2][0] = fma2(qr, kp0, acc[2][0]); acc[2][1] = fma2(qr, kp1, acc[2][1]);
            qr = pk2(q4.w, q4.w); acc[3][0] = fma2(qr, kp0, acc[3][0]); acc[3][1] = fma2(qr, kp1, acc[3][1]);
        }

        // ---- logits = (2 q.k - kk)/sqrt(D); online softmax; write P tile ----
        const float kk0 = kks[tx * 4 + 0];
        const float kk1 = kks[tx * 4 + 1];
        const float kk2 = kks[tx * 4 + 2];
        const float kk3 = kks[tx * 4 + 3];
        float t[4][4];
        #pragma unroll
        for (int r = 0; r < 4; r++) {
            float2 s01 = upk2(acc[r][0]);
            float2 s23 = upk2(acc[r][1]);
            t[r][0] = fmaf(0.25f, s01.x, -0.125f * kk0);
            t[r][1] = fmaf(0.25f, s01.y, -0.125f * kk1);
            t[r][2] = fmaf(0.25f, s23.x, -0.125f * kk2);
            t[r][3] = fmaf(0.25f, s23.y, -0.125f * kk3);
        }
        #pragma unroll
        for (int r = 0; r < 4; r++) {
            float tm = fmaxf(fmaxf(t[r][0], t[r][1]), fmaxf(t[r][2], t[r][3]));
            tm = fmaxf(tm, __shfl_xor_sync(FULLMASK, tm, 8));
            tm = fmaxf(tm, __shfl_xor_sync(FULLMASK, tm, 4));
            tm = fmaxf(tm, __shfl_xor_sync(FULLMASK, tm, 2));
            tm = fmaxf(tm, __shfl_xor_sync(FULLMASK, tm, 1));
            float mn    = fmaxf(row_max[r], tm);
            float alpha = __expf(row_max[r] - mn);
            row_max[r]  = mn;
            float p0 = __expf(t[r][0] - mn);
            float p1 = __expf(t[r][1] - mn);
            float p2 = __expf(t[r][2] - mn);
            float p3 = __expf(t[r][3] - mn);
            float* pr = Ps + (ty * 4 + r) * PSTR + tx * 4;
            pr[0] = p0; pr[1] = p1; pr[2] = p2; pr[3] = p3;
            row_sum[r] = row_sum[r] * alpha + ((p0 + p1) + (p2 + p3));
            u64 a2 = pk2(alpha, alpha);
            o[r][0] = mul2(o[r][0], a2);
            o[r][1] = mul2(o[r][1], a2);
        }
        __syncthreads();

        // ---- O += P . V  (rows from P broadcast, V conflict-free) ----
        #pragma unroll 16
        for (int n = 0; n < BN; n++) {
            float4 v4 = *(const float4*)(Vs + n * STR + tx * 4);
            u64 vp0 = pk2(v4.x, v4.y);
            u64 vp1 = pk2(v4.z, v4.w);
            #pragma unroll
            for (int r = 0; r < 4; r++) {
                float p = Ps[(ty * 4 + r) * PSTR + n];
                u64 pp = pk2(p, p);
                o[r][0] = fma2(pp, vp0, o[r][0]);
                o[r][1] = fma2(pp, vp1, o[r][1]);
            }
        }
        __syncthreads();
    }

    // ---- finalize: reduce row sums across the 16 lanes of each row, write [B,N,H,D] ----
    #pragma unroll
    for (int r = 0; r < 4; r++) {
        float l = row_sum[r];
        l += __shfl_xor_sync(FULLMASK, l, 8);
        l += __shfl_xor_sync(FULLMASK, l, 4);
        l += __shfl_xor_sync(FULLMASK, l, 2);
        l += __shfl_xor_sync(FULLMASK, l, 1);
        float inv = 1.0f / l;
        float2 o01 = upk2(o[r][0]);
        float2 o23 = upk2(o[r][1]);
        float4 res;
        res.x = o01.x * inv; res.y = o01.y * inv;
        res.z = o23.x * inv; res.w = o23.y * inv;
        const int m = m0 + ty * 4 + r;
        size_t oidx = ((size_t)(b * Nn + m) * Hh + h) * Dd + tx * 4;
        *(float4*)(outg + oidx) = res;
    }
}

extern "C" void kernel_launch(void* const* d_in, const int* in_sizes, int n_in,
                              void* d_out, int out_size) {
    (void)in_sizes; (void)n_in; (void)out_size;
    const float* q = (const float*)d_in[0];
    const float* k = (const float*)d_in[1];
    const float* v = (const float*)d_in[2];
    float* out = (float*)d_out;

    cudaFuncSetAttribute(pe_dist_attn_kernel,
                         cudaFuncAttributeMaxDynamicSharedMemorySize, SMEM_BYTES);
    dim3 grid(Nn / BM, 4 * Hh);  // 32 query tiles x (B*H = 32)
    pe_dist_attn_kernel<<<grid, 256, SMEM_BYTES>>>(q, k, v, out);
}

// round 3
// speedup vs baseline: 2.8247x; 2.8247x over previous
#include <cuda_runtime.h>
#include <cuda_bf16.h>
#include <cstdint>

// ============================ problem dims ============================
static constexpr int B_ = 4, H_ = 8, N_ = 2048, D_ = 64;
static constexpr int BH = B_ * H_;   // 32
static constexpr int BM = 128;       // query rows per CTA
static constexpr int BN = 64;        // keys per tile
static constexpr int MT = N_ / BM;   // 16
static constexpr int NT = N_ / BN;   // 32

// ==================== pre-converted gmem scratch ======================
// SW128-preswizzled bf16 tile images: main kernel does pure 16B cp.async.
__device__ __align__(128) uint8_t g_qhi[(size_t)BH * MT * 16384];
__device__ __align__(128) uint8_t g_qlo[(size_t)BH * MT * 16384];
__device__ __align__(128) uint8_t g_khi[(size_t)BH * NT * 8192];
__device__ __align__(128) uint8_t g_klo[(size_t)BH * NT * 8192];
__device__ __align__(128) uint8_t g_vhi[(size_t)BH * NT * 8192];
__device__ __align__(128) uint8_t g_vlo[(size_t)BH * NT * 8192];
__device__ float g_kk[(size_t)BH * N_];   // holds -0.125 * ||k||^2

// ============================ helpers =============================
__device__ __forceinline__ uint32_t smem_u32(const void* p) {
    uint32_t a;
    asm("{ .reg .u64 t; cvta.to.shared.u64 t, %1; cvt.u32.u64 %0, t; }" : "=r"(a) : "l"(p));
    return a;
}
__device__ __forceinline__ void cpa16(uint32_t s, const void* g) {
    asm volatile("cp.async.cg.shared.global [%0], [%1], 16;" :: "r"(s), "l"(g));
}
__device__ __forceinline__ void cpa_commit() { asm volatile("cp.async.commit_group;" ::: "memory"); }
__device__ __forceinline__ void cpa_wait0()  { asm volatile("cp.async.wait_group 0;" ::: "memory"); }
__device__ __forceinline__ void cpa_wait1()  { asm volatile("cp.async.wait_group 1;" ::: "memory"); }

__device__ __forceinline__ void ldmx4(uint32_t* r, uint32_t a) {
    asm volatile("ldmatrix.sync.aligned.m8n8.x4.shared.b16 {%0,%1,%2,%3}, [%4];"
                 : "=r"(r[0]), "=r"(r[1]), "=r"(r[2]), "=r"(r[3]) : "r"(a));
}
__device__ __forceinline__ void ldmx4t(uint32_t* r, uint32_t a) {
    asm volatile("ldmatrix.sync.aligned.m8n8.x4.trans.shared.b16 {%0,%1,%2,%3}, [%4];"
                 : "=r"(r[0]), "=r"(r[1]), "=r"(r[2]), "=r"(r[3]) : "r"(a));
}
// D += A * B  (m16n8k16, bf16 in, fp32 accum)
__device__ __forceinline__ void mma16816(float* c, const uint32_t* a, uint32_t b0, uint32_t b1) {
    asm volatile("mma.sync.aligned.m16n8k16.row.col.f32.bf16.bf16.f32 "
                 "{%0,%1,%2,%3}, {%4,%5,%6,%7}, {%8,%9}, {%0,%1,%2,%3};"
                 : "+f"(c[0]), "+f"(c[1]), "+f"(c[2]), "+f"(c[3])
                 : "r"(a[0]), "r"(a[1]), "r"(a[2]), "r"(a[3]), "r"(b0), "r"(b1));
}
// pack two fp32 into bf16x2 (up -> upper 16 bits, low -> lower 16 bits)
__device__ __forceinline__ uint32_t pkbf2(float up, float low) {
    uint32_t d;
    asm("cvt.rn.bf16x2.f32 %0, %1, %2;" : "=r"(d) : "f"(up), "f"(low));
    return d;
}
__device__ __forceinline__ float lo_f32(uint32_t p) { return __uint_as_float(p << 16); }
__device__ __forceinline__ float hi_f32(uint32_t p) { return __uint_as_float(p & 0xffff0000u); }

// ====================== pre-pass: fp32 -> SW128 bf16 hi/lo images ======================
__device__ __forceinline__ void split_row8(const float* src, uint8_t* dh, uint8_t* dl,
                                           uint32_t rowoff128, float* sumsq) {
    #pragma unroll
    for (int d0 = 0; d0 < 64; d0 += 8) {
        float xs[8];
        *(float4*)(xs)     = *(const float4*)(src + d0);
        *(float4*)(xs + 4) = *(const float4*)(src + d0 + 4);
        uint32_t hp[4], lp[4];
        #pragma unroll
        for (int j = 0; j < 4; j++) {
            float x0 = xs[2 * j], x1 = xs[2 * j + 1];
            if (sumsq) *sumsq += x0 * x0 + x1 * x1;
            uint32_t hpair = pkbf2(x1, x0);
            float l0 = x0 - lo_f32(hpair);
            float l1 = x1 - hi_f32(hpair);
            hp[j] = hpair;
            lp[j] = pkbf2(l1, l0);
        }
        uint32_t x = rowoff128 + d0 * 2;
        uint32_t off = x ^ ((x >> 3) & 0x70);
        *(uint4*)(dh + off) = make_uint4(hp[0], hp[1], hp[2], hp[3]);
        *(uint4*)(dl + off) = make_uint4(lp[0], lp[1], lp[2], lp[3]);
    }
}

__global__ void prep_kernel(const float* __restrict__ q, const float* __restrict__ k,
                            const float* __restrict__ v) {
    int idx = blockIdx.x * 256 + threadIdx.x;   // 0 .. BH*N-1
    int bh = idx >> 11, n = idx & 2047;

    {   // Q row
        int mt = n >> 7, r = n & 127;
        split_row8(q + (size_t)idx * 64,
                   g_qhi + (((size_t)(bh * MT + mt)) << 14),
                   g_qlo + (((size_t)(bh * MT + mt)) << 14),
                   (uint32_t)r * 128, nullptr);
    }
    {   // K row + kk
        int nt = n >> 6, r = n & 63;
        float kk = 0.f;
        split_row8(k + (size_t)idx * 64,
                   g_khi + (((size_t)(bh * NT + nt)) << 13),
                   g_klo + (((size_t)(bh * NT + nt)) << 13),
                   (uint32_t)r * 128, &kk);
        g_kk[idx] = -0.125f * kk;
    }
    {   // V row (same layout as K)
        int nt = n >> 6, r = n & 63;
        split_row8(v + (size_t)idx * 64,
                   g_vhi + (((size_t)(bh * NT + nt)) << 13),
                   g_vlo + (((size_t)(bh * NT + nt)) << 13),
                   (uint32_t)r * 128, nullptr);
    }
}

// =========================== main kernel ===========================
// smem layout (bytes)
static constexpr uint32_t S_QHI = 0;        // 16KB
static constexpr uint32_t S_QLO = 16384;    // 16KB
static constexpr uint32_t S_KV  = 32768;    // 2 bufs x 32KB: khi@0 klo@8192 vhi@16384 vlo@24576
static constexpr uint32_t S_KK  = 98304;    // 2 x 256B
static constexpr uint32_t SMEM_BYTES = 98304 + 512;

__global__ __launch_bounds__(256)
void attn_main(float* __restrict__ out) {
    extern __shared__ __align__(1024) uint8_t smem[];
    const uint32_t sb = smem_u32(smem);
    const int tid = threadIdx.x, wid = tid >> 5, lane = tid & 31;
    const int mt = blockIdx.x, bh = blockIdx.y;
    const int b = bh >> 3, h = bh & 7;
    const int mrank = lane >> 3;         // ldmatrix matrix index of this lane
    const int l7 = lane & 7;

    // ---- prologue: Q images + tile 0 ----
    {
        const uint8_t* qh = g_qhi + (((size_t)(bh * MT + mt)) << 14);
        const uint8_t* ql = g_qlo + (((size_t)(bh * MT + mt)) << 14);
        #pragma unroll
        for (int i = 0; i < 4; i++) {
            int o = (tid + 256 * i) * 16;
            cpa16(sb + S_QHI + o, qh + o);
            cpa16(sb + S_QLO + o, ql + o);
        }
        const size_t t0 = ((size_t)(bh * NT)) << 13;
        #pragma unroll
        for (int i = 0; i < 2; i++) {
            int o = (tid + 256 * i) * 16;
            cpa16(sb + S_KV +          o, g_khi + t0 + o);
            cpa16(sb + S_KV +  8192 + o, g_klo + t0 + o);
            cpa16(sb + S_KV + 16384 + o, g_vhi + t0 + o);
            cpa16(sb + S_KV + 24576 + o, g_vlo + t0 + o);
        }
        if (tid < 16) cpa16(sb + S_KK + tid * 16, g_kk + (size_t)bh * N_ + tid * 4);
        cpa_commit();
        cpa_wait0();
    }
    __syncthreads();

    // ---- Q A-fragments (persist in registers) ----
    uint32_t Qh[4][4], Ql[4][4];
    {
        int qrow = wid * 16 + ((mrank & 1) << 3) + l7;
        uint32_t rbase = (uint32_t)qrow * 128;
        uint32_t rx = (uint32_t)((qrow & 7) << 4);
        #pragma unroll
        for (int ks = 0; ks < 4; ks++) {
            uint32_t colb = (uint32_t)(ks * 32 + ((mrank >> 1) << 4));
            uint32_t a = sb + S_QHI + rbase + (colb ^ rx);
            ldmx4(Qh[ks], a);
            ldmx4(Ql[ks], a + 16384);
        }
    }

    float O[8][4];
    #pragma unroll
    for (int i = 0; i < 8; i++)
        #pragma unroll
        for (int j = 0; j < 4; j++) O[i][j] = 0.f;
    float Lp0 = 0.f, Lp1 = 0.f;

    // precomputed per-lane ldmatrix row offsets within a 16-row block
    const int krow16 = ((mrank >> 1) << 3) + l7;        // K (non-trans): rows split by m>>1
    const int vrow16 = ((mrank & 1) << 3) + l7;         // V (trans): rows split by m&1
    const uint32_t kcol = (uint32_t)((mrank & 1) << 4); // K col sub-block
    const uint32_t vcol = (uint32_t)((mrank >> 1) << 4);

    for (int kt = 0; kt < NT; kt++) {
        const uint32_t cb = sb + S_KV + (uint32_t)(kt & 1) * 32768;

        // prefetch tile kt+1
        if (kt + 1 < NT) {
            const size_t toff = ((size_t)(bh * NT + kt + 1)) << 13;
            const uint32_t dst = sb + S_KV + (uint32_t)((kt + 1) & 1) * 32768;
            #pragma unroll
            for (int i = 0; i < 2; i++) {
                int o = (tid + 256 * i) * 16;
                cpa16(dst +          o, g_khi + toff + o);
                cpa16(dst +  8192 + o, g_klo + toff + o);
                cpa16(dst + 16384 + o, g_vhi + toff + o);
                cpa16(dst + 24576 + o, g_vlo + toff + o);
            }
            if (tid < 16) cpa16(sb + S_KK + ((kt + 1) & 1) * 256 + tid * 16,
                                g_kk + (size_t)bh * N_ + (size_t)(kt + 1) * 64 + tid * 4);
        }
        cpa_commit();
        cpa_wait1();
        __syncthreads();

        // ================ S = Q . K^T (3-term split) ================
        float S[8][4];
        #pragma unroll
        for (int i = 0; i < 8; i++)
            #pragma unroll
            for (int j = 0; j < 4; j++) S[i][j] = 0.f;

        #pragma unroll
        for (int ks = 0; ks < 4; ks++) {
            #pragma unroll
            for (int np = 0; np < 4; np++) {
                int row = np * 16 + krow16;
                uint32_t colb = (uint32_t)(ks * 32) + kcol;
                uint32_t a = cb + (uint32_t)row * 128 + (colb ^ (uint32_t)((row & 7) << 4));
                uint32_t KBh[4], KBl[4];
                ldmx4(KBh, a);
                ldmx4(KBl, a + 8192);
                mma16816(S[2 * np],     Qh[ks], KBh[0], KBh[1]);
                mma16816(S[2 * np + 1], Qh[ks], KBh[2], KBh[3]);
                mma16816(S[2 * np],     Ql[ks], KBh[0], KBh[1]);
                mma16816(S[2 * np + 1], Ql[ks], KBh[2], KBh[3]);
                mma16816(S[2 * np],     Qh[ks], KBl[0], KBl[1]);
                mma16816(S[2 * np + 1], Qh[ks], KBl[2], KBl[3]);
            }
        }

        // ================ softmax numerator -> P A-fragments ================
        const float* kkp = (const float*)(smem + S_KK + (kt & 1) * 256);
        uint32_t Ph[4][4], Pl[4][4];
        #pragma unroll
        for (int nt = 0; nt < 8; nt++) {
            int col = nt * 8 + 2 * (lane & 3);
            float k0 = kkp[col], k1 = kkp[col + 1];
            float p0 = __expf(fmaf(0.25f, S[nt][0], k0));
            float p1 = __expf(fmaf(0.25f, S[nt][1], k1));
            float p2 = __expf(fmaf(0.25f, S[nt][2], k0));
            float p3 = __expf(fmaf(0.25f, S[nt][3], k1));
            Lp0 += p0 + p1;
            Lp1 += p2 + p3;
            uint32_t h01 = pkbf2(p1, p0);
            uint32_t h23 = pkbf2(p3, p2);
            uint32_t l01 = pkbf2(p1 - hi_f32(h01), p0 - lo_f32(h01));
            uint32_t l23 = pkbf2(p3 - hi_f32(h23), p2 - lo_f32(h23));
            Ph[nt >> 1][(nt & 1) * 2]     = h01;
            Ph[nt >> 1][(nt & 1) * 2 + 1] = h23;
            Pl[nt >> 1][(nt & 1) * 2]     = l01;
            Pl[nt >> 1][(nt & 1) * 2 + 1] = l23;
        }

        // ================ O += P . V (3-term split) ================
        #pragma unroll
        for (int j = 0; j < 4; j++) {
            #pragma unroll
            for (int dp = 0; dp < 4; dp++) {
                int row = j * 16 + vrow16;
                uint32_t colb = (uint32_t)(dp * 32) + vcol;
                uint32_t a = cb + 16384 + (uint32_t)row * 128 + (colb ^ (uint32_t)((row & 7) << 4));
                uint32_t VBh[4], VBl[4];
                ldmx4t(VBh, a);
                ldmx4t(VBl, a + 8192);
                mma16816(O[2 * dp],     Ph[j], VBh[0], VBh[1]);
                mma16816(O[2 * dp + 1], Ph[j], VBh[2], VBh[3]);
                mma16816(O[2 * dp],     Pl[j], VBh[0], VBh[1]);
                mma16816(O[2 * dp + 1], Pl[j], VBh[2], VBh[3]);
                mma16816(O[2 * dp],     Ph[j], VBl[0], VBl[1]);
                mma16816(O[2 * dp + 1], Ph[j], VBl[2], VBl[3]);
            }
        }
        __syncthreads();
    }

    // ---- epilogue: reduce row sums across quads, normalize, store ----
    Lp0 += __shfl_xor_sync(0xffffffffu, Lp0, 1);
    Lp0 += __shfl_xor_sync(0xffffffffu, Lp0, 2);
    Lp1 += __shfl_xor_sync(0xffffffffu, Lp1, 1);
    Lp1 += __shfl_xor_sync(0xffffffffu, Lp1, 2);
    float inv0 = 1.0f / Lp0;
    float inv1 = 1.0f / Lp1;

    const int r0 = mt * 128 + wid * 16 + (lane >> 2);
    const int dbase = 2 * (lane & 3);
    float* o0 = out + (((size_t)(b * N_ + r0) * H_ + h) << 6);
    float* o1 = out + (((size_t)(b * N_ + r0 + 8) * H_ + h) << 6);
    #pragma unroll
    for (int dt = 0; dt < 8; dt++) {
        int d = dt * 8 + dbase;
        float2 a0 = make_float2(O[dt][0] * inv0, O[dt][1] * inv0);
        float2 a1 = make_float2(O[dt][2] * inv1, O[dt][3] * inv1);
        *(float2*)(o0 + d) = a0;
        *(float2*)(o1 + d) = a1;
    }
}

// ============================ launch ============================
extern "C" void kernel_launch(void* const* d_in, const int* in_sizes, int n_in,
                              void* d_out, int out_size) {
    (void)in_sizes; (void)n_in; (void)out_size;
    const float* q = (const float*)d_in[0];
    const float* k = (const float*)d_in[1];
    const float* v = (const float*)d_in[2];
    float* out = (float*)d_out;

    prep_kernel<<<BH * N_ / 256, 256>>>(q, k, v);

    cudaFuncSetAttribute(attn_main, cudaFuncAttributeMaxDynamicSharedMemorySize, SMEM_BYTES);
    dim3 grid(MT, BH);
    attn_main<<<grid, 256, SMEM_BYTES>>>(out);
}

// round 4
// speedup vs baseline: 3.2565x; 1.1529x over previous
#include <cuda_runtime.h>
#include <cuda_bf16.h>
#include <cstdint>

// ============================ problem dims ============================
static constexpr int B_ = 4, H_ = 8, N_ = 2048, D_ = 64;
static constexpr int BH = B_ * H_;   // 32
static constexpr int BM = 64;        // query rows per CTA
static constexpr int BN = 64;        // keys per tile
static constexpr int MT = N_ / BM;   // 32
static constexpr int NT = N_ / BN;   // 32

// ==================== pre-converted gmem scratch ======================
// SW128-preswizzled bf16 tile images: main kernel does pure 16B cp.async.
// Q image: per (bh, mt): 64 rows x 128B = 8KB. K/V: per (bh, nt): 64 x 128B = 8KB.
__device__ __align__(128) uint8_t g_qhi[(size_t)BH * MT * 8192];
__device__ __align__(128) uint8_t g_qlo[(size_t)BH * MT * 8192];
__device__ __align__(128) uint8_t g_khi[(size_t)BH * NT * 8192];
__device__ __align__(128) uint8_t g_klo[(size_t)BH * NT * 8192];
__device__ __align__(128) uint8_t g_vhi[(size_t)BH * NT * 8192];
__device__ __align__(128) uint8_t g_vlo[(size_t)BH * NT * 8192];
__device__ float g_kk[(size_t)BH * N_];   // holds -0.125 * log2(e) * ||k||^2

// ============================ helpers =============================
__device__ __forceinline__ uint32_t smem_u32(const void* p) {
    uint32_t a;
    asm("{ .reg .u64 t; cvta.to.shared.u64 t, %1; cvt.u32.u64 %0, t; }" : "=r"(a) : "l"(p));
    return a;
}
__device__ __forceinline__ void cpa16(uint32_t s, const void* g) {
    asm volatile("cp.async.cg.shared.global [%0], [%1], 16;" :: "r"(s), "l"(g));
}
__device__ __forceinline__ void cpa_commit() { asm volatile("cp.async.commit_group;" ::: "memory"); }
__device__ __forceinline__ void cpa_wait0()  { asm volatile("cp.async.wait_group 0;" ::: "memory"); }
__device__ __forceinline__ void cpa_wait1()  { asm volatile("cp.async.wait_group 1;" ::: "memory"); }

__device__ __forceinline__ void ldmx4(uint32_t* r, uint32_t a) {
    asm volatile("ldmatrix.sync.aligned.m8n8.x4.shared.b16 {%0,%1,%2,%3}, [%4];"
                 : "=r"(r[0]), "=r"(r[1]), "=r"(r[2]), "=r"(r[3]) : "r"(a));
}
__device__ __forceinline__ void ldmx4t(uint32_t* r, uint32_t a) {
    asm volatile("ldmatrix.sync.aligned.m8n8.x4.trans.shared.b16 {%0,%1,%2,%3}, [%4];"
                 : "=r"(r[0]), "=r"(r[1]), "=r"(r[2]), "=r"(r[3]) : "r"(a));
}
// D += A * B  (m16n8k16, bf16 in, fp32 accum)
__device__ __forceinline__ void mma16816(float* c, const uint32_t* a, uint32_t b0, uint32_t b1) {
    asm volatile("mma.sync.aligned.m16n8k16.row.col.f32.bf16.bf16.f32 "
                 "{%0,%1,%2,%3}, {%4,%5,%6,%7}, {%8,%9}, {%0,%1,%2,%3};"
                 : "+f"(c[0]), "+f"(c[1]), "+f"(c[2]), "+f"(c[3])
                 : "r"(a[0]), "r"(a[1]), "r"(a[2]), "r"(a[3]), "r"(b0), "r"(b1));
}
__device__ __forceinline__ uint32_t pkbf2(float up, float low) {
    uint32_t d;
    asm("cvt.rn.bf16x2.f32 %0, %1, %2;" : "=r"(d) : "f"(up), "f"(low));
    return d;
}
__device__ __forceinline__ float lo_f32(uint32_t p) { return __uint_as_float(p << 16); }
__device__ __forceinline__ float hi_f32(uint32_t p) { return __uint_as_float(p & 0xffff0000u); }
__device__ __forceinline__ float ex2f(float x) {
    float y;
    asm("ex2.approx.f32 %0, %1;" : "=f"(y) : "f"(x));
    return y;
}
static constexpr float LOG2E   = 1.4426950408889634f;
static constexpr float SCALE_S = 0.25f * LOG2E;    // applied to raw 2*q.k accumulator (x0.5 inside)

// ====================== pre-pass: fp32 -> SW128 bf16 hi/lo images ======================
// 8 threads per row: thread handles one 16B chunk (8 elements). Fully coalesced.
__global__ void prep_kernel(const float* __restrict__ q, const float* __restrict__ k,
                            const float* __restrict__ v) {
    int idx  = blockIdx.x * 256 + threadIdx.x;   // 0 .. BH*N*8-1
    int rown = idx >> 3;                          // global row 0..65535
    int c    = idx & 7;                           // chunk within row
    int d0   = c * 8;
    int bh = rown >> 11, n = rown & 2047;

    auto split8 = [&](const float* src, uint8_t* dh, uint8_t* dl, uint32_t rowoff, float* ss) {
        float xs[8];
        *(float4*)(xs)     = *(const float4*)(src);
        *(float4*)(xs + 4) = *(const float4*)(src + 4);
        uint32_t hp[4], lp[4];
        #pragma unroll
        for (int j = 0; j < 4; j++) {
            float x0 = xs[2 * j], x1 = xs[2 * j + 1];
            if (ss) *ss += x0 * x0 + x1 * x1;
            uint32_t hpair = pkbf2(x1, x0);
            hp[j] = hpair;
            lp[j] = pkbf2(x1 - hi_f32(hpair), x0 - lo_f32(hpair));
        }
        uint32_t x = rowoff + (uint32_t)d0 * 2;
        uint32_t off = x ^ ((x >> 3) & 0x70);
        *(uint4*)(dh + off) = make_uint4(hp[0], hp[1], hp[2], hp[3]);
        *(uint4*)(dl + off) = make_uint4(lp[0], lp[1], lp[2], lp[3]);
    };

    {   // Q
        int mt = n >> 7 ? 0 : 0; (void)mt;
        int qmt = n >> 6, r = n & 63;   // BM=64 tiles
        split8(q + (size_t)rown * 64 + d0,
               g_qhi + (((size_t)(bh * MT + qmt)) << 13),
               g_qlo + (((size_t)(bh * MT + qmt)) << 13),
               (uint32_t)r * 128, nullptr);
    }
    {   // K + kk
        int nt = n >> 6, r = n & 63;
        float ss = 0.f;
        split8(k + (size_t)rown * 64 + d0,
               g_khi + (((size_t)(bh * NT + nt)) << 13),
               g_klo + (((size_t)(bh * NT + nt)) << 13),
               (uint32_t)r * 128, &ss);
        ss += __shfl_xor_sync(0xffffffffu, ss, 1);
        ss += __shfl_xor_sync(0xffffffffu, ss, 2);
        ss += __shfl_xor_sync(0xffffffffu, ss, 4);
        if (c == 0) g_kk[rown] = -0.125f * LOG2E * ss;
    }
    {   // V
        int nt = n >> 6, r = n & 63;
        split8(v + (size_t)rown * 64 + d0,
               g_vhi + (((size_t)(bh * NT + nt)) << 13),
               g_vlo + (((size_t)(bh * NT + nt)) << 13),
               (uint32_t)r * 128, nullptr);
    }
}

// =========================== main kernel ===========================
// smem layout (bytes)
static constexpr uint32_t S_QHI = 0;        // 8KB
static constexpr uint32_t S_QLO = 8192;     // 8KB
static constexpr uint32_t S_KV  = 16384;    // 2 bufs x 32KB: khi@0 klo@8192 vhi@16384 vlo@24576
static constexpr uint32_t S_KK  = 81920;    // 2 x 256B
static constexpr uint32_t SMEM_BYTES = 81920 + 512;

__global__ __launch_bounds__(128)
void attn_main(float* __restrict__ out) {
    extern __shared__ __align__(1024) uint8_t smem[];
    const uint32_t sb = smem_u32(smem);
    const int tid = threadIdx.x, wid = tid >> 5, lane = tid & 31;
    const int mt = blockIdx.x, bh = blockIdx.y;
    const int b = bh >> 3, h = bh & 7;
    const int mrank = lane >> 3;
    const int l7 = lane & 7;

    // ---- prologue: Q images + tile 0 ----
    {
        const uint8_t* qh = g_qhi + (((size_t)(bh * MT + mt)) << 13);
        const uint8_t* ql = g_qlo + (((size_t)(bh * MT + mt)) << 13);
        #pragma unroll
        for (int i = 0; i < 4; i++) {
            int o = (tid + 128 * i) * 16;
            cpa16(sb + S_QHI + o, qh + o);
            cpa16(sb + S_QLO + o, ql + o);
        }
        const size_t t0 = ((size_t)(bh * NT)) << 13;
        #pragma unroll
        for (int i = 0; i < 4; i++) {
            int o = (tid + 128 * i) * 16;
            cpa16(sb + S_KV +          o, g_khi + t0 + o);
            cpa16(sb + S_KV +  8192 + o, g_klo + t0 + o);
            cpa16(sb + S_KV + 16384 + o, g_vhi + t0 + o);
            cpa16(sb + S_KV + 24576 + o, g_vlo + t0 + o);
        }
        if (tid < 16) cpa16(sb + S_KK + tid * 16, g_kk + (size_t)bh * N_ + tid * 4);
        cpa_commit();
        cpa_wait0();
    }
    __syncthreads();

    // ---- Q A-fragments (persist in registers) ----
    uint32_t Qh[4][4], Ql[4][4];
    {
        int qrow = wid * 16 + ((mrank & 1) << 3) + l7;
        uint32_t rbase = (uint32_t)qrow * 128;
        uint32_t rx = (uint32_t)((qrow & 7) << 4);
        #pragma unroll
        for (int ks = 0; ks < 4; ks++) {
            uint32_t colb = (uint32_t)(ks * 32 + ((mrank >> 1) << 4));
            uint32_t a = sb + S_QHI + rbase + (colb ^ rx);
            ldmx4(Qh[ks], a);
            ldmx4(Ql[ks], a + 8192);
        }
    }

    float O[8][4];
    #pragma unroll
    for (int i = 0; i < 8; i++)
        #pragma unroll
        for (int j = 0; j < 4; j++) O[i][j] = 0.f;
    float Lp0 = 0.f, Lp1 = 0.f;

    const int krow16 = ((mrank >> 1) << 3) + l7;
    const int vrow16 = ((mrank & 1) << 3) + l7;
    const uint32_t kcol = (uint32_t)((mrank & 1) << 4);
    const uint32_t vcol = (uint32_t)((mrank >> 1) << 4);

    for (int kt = 0; kt < NT; kt++) {
        const uint32_t cb = sb + S_KV + (uint32_t)(kt & 1) * 32768;

        // prefetch tile kt+1
        if (kt + 1 < NT) {
            const size_t toff = ((size_t)(bh * NT + kt + 1)) << 13;
            const uint32_t dst = sb + S_KV + (uint32_t)((kt + 1) & 1) * 32768;
            #pragma unroll
            for (int i = 0; i < 4; i++) {
                int o = (tid + 128 * i) * 16;
                cpa16(dst +          o, g_khi + toff + o);
                cpa16(dst +  8192 + o, g_klo + toff + o);
                cpa16(dst + 16384 + o, g_vhi + toff + o);
                cpa16(dst + 24576 + o, g_vlo + toff + o);
            }
            if (tid < 16) cpa16(sb + S_KK + ((kt + 1) & 1) * 256 + tid * 16,
                                g_kk + (size_t)bh * N_ + (size_t)(kt + 1) * 64 + tid * 4);
        }
        cpa_commit();
        cpa_wait1();
        __syncthreads();

        // ================ S = Q . K^T (3-term split) ================
        float S[8][4];
        #pragma unroll
        for (int i = 0; i < 8; i++)
            #pragma unroll
            for (int j = 0; j < 4; j++) S[i][j] = 0.f;

        #pragma unroll
        for (int ks = 0; ks < 4; ks++) {
            #pragma unroll
            for (int np = 0; np < 4; np++) {
                int row = np * 16 + krow16;
                uint32_t colb = (uint32_t)(ks * 32) + kcol;
                uint32_t a = cb + (uint32_t)row * 128 + (colb ^ (uint32_t)((row & 7) << 4));
                uint32_t KBh[4], KBl[4];
                ldmx4(KBh, a);
                ldmx4(KBl, a + 8192);
                mma16816(S[2 * np],     Qh[ks], KBh[0], KBh[1]);
                mma16816(S[2 * np + 1], Qh[ks], KBh[2], KBh[3]);
                mma16816(S[2 * np],     Ql[ks], KBh[0], KBh[1]);
                mma16816(S[2 * np + 1], Ql[ks], KBh[2], KBh[3]);
                mma16816(S[2 * np],     Qh[ks], KBl[0], KBl[1]);
                mma16816(S[2 * np + 1], Qh[ks], KBl[2], KBl[3]);
            }
        }

        // ================ softmax numerator -> P A-fragments ================
        const float* kkp = (const float*)(smem + S_KK + (kt & 1) * 256);
        uint32_t Ph[4][4], Pl[4][4];
        #pragma unroll
        for (int nt = 0; nt < 8; nt++) {
            int col = nt * 8 + 2 * (lane & 3);
            float k0 = kkp[col], k1 = kkp[col + 1];
            float p0 = ex2f(fmaf(SCALE_S, S[nt][0], k0));
            float p1 = ex2f(fmaf(SCALE_S, S[nt][1], k1));
            float p2 = ex2f(fmaf(SCALE_S, S[nt][2], k0));
            float p3 = ex2f(fmaf(SCALE_S, S[nt][3], k1));
            Lp0 += p0 + p1;
            Lp1 += p2 + p3;
            uint32_t h01 = pkbf2(p1, p0);
            uint32_t h23 = pkbf2(p3, p2);
            uint32_t l01 = pkbf2(p1 - hi_f32(h01), p0 - lo_f32(h01));
            uint32_t l23 = pkbf2(p3 - hi_f32(h23), p2 - lo_f32(h23));
            Ph[nt >> 1][(nt & 1) * 2]     = h01;
            Ph[nt >> 1][(nt & 1) * 2 + 1] = h23;
            Pl[nt >> 1][(nt & 1) * 2]     = l01;
            Pl[nt >> 1][(nt & 1) * 2 + 1] = l23;
        }

        // ================ O += P . V (3-term split) ================
        #pragma unroll
        for (int j = 0; j < 4; j++) {
            #pragma unroll
            for (int dp = 0; dp < 4; dp++) {
                int row = j * 16 + vrow16;
                uint32_t colb = (uint32_t)(dp * 32) + vcol;
                uint32_t a = cb + 16384 + (uint32_t)row * 128 + (colb ^ (uint32_t)((row & 7) << 4));
                uint32_t VBh[4], VBl[4];
                ldmx4t(VBh, a);
                ldmx4t(VBl, a + 8192);
                mma16816(O[2 * dp],     Ph[j], VBh[0], VBh[1]);
                mma16816(O[2 * dp + 1], Ph[j], VBh[2], VBh[3]);
                mma16816(O[2 * dp],     Pl[j], VBh[0], VBh[1]);
                mma16816(O[2 * dp + 1], Pl[j], VBh[2], VBh[3]);
                mma16816(O[2 * dp],     Ph[j], VBl[0], VBl[1]);
                mma16816(O[2 * dp + 1], Ph[j], VBl[2], VBl[3]);
            }
        }
        __syncthreads();
    }

    // ---- epilogue: reduce row sums across quads, normalize, store ----
    Lp0 += __shfl_xor_sync(0xffffffffu, Lp0, 1);
    Lp0 += __shfl_xor_sync(0xffffffffu, Lp0, 2);
    Lp1 += __shfl_xor_sync(0xffffffffu, Lp1, 1);
    Lp1 += __shfl_xor_sync(0xffffffffu, Lp1, 2);
    float inv0 = 1.0f / Lp0;
    float inv1 = 1.0f / Lp1;

    const int r0 = mt * BM + wid * 16 + (lane >> 2);
    const int dbase = 2 * (lane & 3);
    float* o0 = out + (((size_t)(b * N_ + r0) * H_ + h) << 6);
    float* o1 = out + (((size_t)(b * N_ + r0 + 8) * H_ + h) << 6);
    #pragma unroll
    for (int dt = 0; dt < 8; dt++) {
        int d = dt * 8 + dbase;
        float2 a0 = make_float2(O[dt][0] * inv0, O[dt][1] * inv0);
        float2 a1 = make_float2(O[dt][2] * inv1, O[dt][3] * inv1);
        *(float2*)(o0 + d) = a0;
        *(float2*)(o1 + d) = a1;
    }
}

// ============================ launch ============================
extern "C" void kernel_launch(void* const* d_in, const int* in_sizes, int n_in,
                              void* d_out, int out_size) {
    (void)in_sizes; (void)n_in; (void)out_size;
    const float* q = (const float*)d_in[0];
    const float* k = (const float*)d_in[1];
    const float* v = (const float*)d_in[2];
    float* out = (float*)d_out;

    prep_kernel<<<BH * N_ * 8 / 256, 256>>>(q, k, v);

    cudaFuncSetAttribute(attn_main, cudaFuncAttributeMaxDynamicSharedMemorySize, SMEM_BYTES);
    dim3 grid(MT, BH);
    attn_main<<<grid, 128, SMEM_BYTES>>>(out);
}

// round 5
// speedup vs baseline: 3.7517x; 1.1521x over previous
#include <cuda_runtime.h>
#include <cuda_bf16.h>
#include <cstdint>

// ============================ problem dims ============================
static constexpr int B_ = 4, H_ = 8, N_ = 2048, D_ = 64;
static constexpr int BH = B_ * H_;   // 32
static constexpr int BM = 64;        // query rows per CTA
static constexpr int BN = 64;        // keys per tile
static constexpr int MT = N_ / BM;   // 32
static constexpr int NT = N_ / BN;   // 32

// ==================== pre-converted gmem scratch ======================
// SW128-preswizzled bf16 tile images: main kernel does pure 16B cp.async.
__device__ __align__(128) uint8_t g_qhi[(size_t)BH * MT * 8192];
__device__ __align__(128) uint8_t g_qlo[(size_t)BH * MT * 8192];
__device__ __align__(128) uint8_t g_khi[(size_t)BH * NT * 8192];
__device__ __align__(128) uint8_t g_klo[(size_t)BH * NT * 8192];
__device__ __align__(128) uint8_t g_vhi[(size_t)BH * NT * 8192];
__device__ __align__(128) uint8_t g_vlo[(size_t)BH * NT * 8192];
__device__ float g_kk[(size_t)BH * N_];   // holds -0.125 * log2(e) * ||k||^2

// ============================ helpers =============================
__device__ __forceinline__ uint32_t smem_u32(const void* p) {
    uint32_t a;
    asm("{ .reg .u64 t; cvta.to.shared.u64 t, %1; cvt.u32.u64 %0, t; }" : "=r"(a) : "l"(p));
    return a;
}
__device__ __forceinline__ void cpa16(uint32_t s, const void* g) {
    asm volatile("cp.async.cg.shared.global [%0], [%1], 16;" :: "r"(s), "l"(g));
}
__device__ __forceinline__ void cpa_commit() { asm volatile("cp.async.commit_group;" ::: "memory"); }
__device__ __forceinline__ void cpa_wait0()  { asm volatile("cp.async.wait_group 0;" ::: "memory"); }
__device__ __forceinline__ void cpa_wait1()  { asm volatile("cp.async.wait_group 1;" ::: "memory"); }

__device__ __forceinline__ void ldmx4(uint32_t* r, uint32_t a) {
    asm volatile("ldmatrix.sync.aligned.m8n8.x4.shared.b16 {%0,%1,%2,%3}, [%4];"
                 : "=r"(r[0]), "=r"(r[1]), "=r"(r[2]), "=r"(r[3]) : "r"(a));
}
__device__ __forceinline__ void ldmx4t(uint32_t* r, uint32_t a) {
    asm volatile("ldmatrix.sync.aligned.m8n8.x4.trans.shared.b16 {%0,%1,%2,%3}, [%4];"
                 : "=r"(r[0]), "=r"(r[1]), "=r"(r[2]), "=r"(r[3]) : "r"(a));
}
// D += A * B  (m16n8k16, bf16 in, fp32 accum)
__device__ __forceinline__ void mma16816(float* c, const uint32_t* a, uint32_t b0, uint32_t b1) {
    asm volatile("mma.sync.aligned.m16n8k16.row.col.f32.bf16.bf16.f32 "
                 "{%0,%1,%2,%3}, {%4,%5,%6,%7}, {%8,%9}, {%0,%1,%2,%3};"
                 : "+f"(c[0]), "+f"(c[1]), "+f"(c[2]), "+f"(c[3])
                 : "r"(a[0]), "r"(a[1]), "r"(a[2]), "r"(a[3]), "r"(b0), "r"(b1));
}
__device__ __forceinline__ uint32_t pkbf2(float up, float low) {
    uint32_t d;
    asm("cvt.rn.bf16x2.f32 %0, %1, %2;" : "=r"(d) : "f"(up), "f"(low));
    return d;
}
__device__ __forceinline__ float lo_f32(uint32_t p) { return __uint_as_float(p << 16); }
__device__ __forceinline__ float hi_f32(uint32_t p) { return __uint_as_float(p & 0xffff0000u); }
__device__ __forceinline__ float ex2f(float x) {
    float y;
    asm("ex2.approx.f32 %0, %1;" : "=f"(y) : "f"(x));
    return y;
}
static constexpr float LOG2E   = 1.4426950408889634f;
static constexpr float SCALE_S = 0.25f * LOG2E;

// ====================== pre-pass: fp32 -> SW128 bf16 hi/lo images ======================
__global__ void prep_kernel(const float* __restrict__ q, const float* __restrict__ k,
                            const float* __restrict__ v) {
    int idx  = blockIdx.x * 256 + threadIdx.x;   // 0 .. BH*N*8-1
    int rown = idx >> 3;
    int c    = idx & 7;
    int d0   = c * 8;
    int bh = rown >> 11, n = rown & 2047;

    auto split8 = [&](const float* src, uint8_t* dh, uint8_t* dl, uint32_t rowoff, float* ss) {
        float xs[8];
        *(float4*)(xs)     = *(const float4*)(src);
        *(float4*)(xs + 4) = *(const float4*)(src + 4);
        uint32_t hp[4], lp[4];
        #pragma unroll
        for (int j = 0; j < 4; j++) {
            float x0 = xs[2 * j], x1 = xs[2 * j + 1];
            if (ss) *ss += x0 * x0 + x1 * x1;
            uint32_t hpair = pkbf2(x1, x0);
            hp[j] = hpair;
            lp[j] = pkbf2(x1 - hi_f32(hpair), x0 - lo_f32(hpair));
        }
        uint32_t x = rowoff + (uint32_t)d0 * 2;
        uint32_t off = x ^ ((x >> 3) & 0x70);
        *(uint4*)(dh + off) = make_uint4(hp[0], hp[1], hp[2], hp[3]);
        *(uint4*)(dl + off) = make_uint4(lp[0], lp[1], lp[2], lp[3]);
    };

    {   // Q
        int qmt = n >> 6, r = n & 63;
        split8(q + (size_t)rown * 64 + d0,
               g_qhi + (((size_t)(bh * MT + qmt)) << 13),
               g_qlo + (((size_t)(bh * MT + qmt)) << 13),
               (uint32_t)r * 128, nullptr);
    }
    {   // K + kk
        int nt = n >> 6, r = n & 63;
        float ss = 0.f;
        split8(k + (size_t)rown * 64 + d0,
               g_khi + (((size_t)(bh * NT + nt)) << 13),
               g_klo + (((size_t)(bh * NT + nt)) << 13),
               (uint32_t)r * 128, &ss);
        ss += __shfl_xor_sync(0xffffffffu, ss, 1);
        ss += __shfl_xor_sync(0xffffffffu, ss, 2);
        ss += __shfl_xor_sync(0xffffffffu, ss, 4);
        if (c == 0) g_kk[rown] = -0.125f * LOG2E * ss;
    }
    {   // V
        int nt = n >> 6, r = n & 63;
        split8(v + (size_t)rown * 64 + d0,
               g_vhi + (((size_t)(bh * NT + nt)) << 13),
               g_vlo + (((size_t)(bh * NT + nt)) << 13),
               (uint32_t)r * 128, nullptr);
    }
}

// =========================== main kernel ===========================
// smem layout (bytes): KV ring of 2 x 32KB at [0,64K).
// Q image staged at [32K,48K) during prologue (inside buf1's footprint),
// consumed into register fragments, then buf1 reuses that space.
static constexpr uint32_t S_KV  = 0;        // bufs at 0 and 32768
static constexpr uint32_t S_QH  = 32768;    // prologue only
static constexpr uint32_t S_QL  = 40960;    // prologue only
static constexpr uint32_t S_KK  = 65536;    // 2 x 256B
static constexpr uint32_t SMEM_BYTES = 65536 + 512;

__global__ __launch_bounds__(128, 3)
void attn_main(float* __restrict__ out) {
    extern __shared__ __align__(1024) uint8_t smem[];
    const uint32_t sb = smem_u32(smem);
    const int tid = threadIdx.x, wid = tid >> 5, lane = tid & 31;
    const int mt = blockIdx.x, bh = blockIdx.y;
    const int b = bh >> 3, h = bh & 7;
    const int mrank = lane >> 3;
    const int l7 = lane & 7;

    // ---- prologue: Q images (staged) + KV tile 0 ----
    {
        const uint8_t* qh = g_qhi + (((size_t)(bh * MT + mt)) << 13);
        const uint8_t* ql = g_qlo + (((size_t)(bh * MT + mt)) << 13);
        #pragma unroll
        for (int i = 0; i < 4; i++) {
            int o = (tid + 128 * i) * 16;
            cpa16(sb + S_QH + o, qh + o);
            cpa16(sb + S_QL + o, ql + o);
        }
        const size_t t0 = ((size_t)(bh * NT)) << 13;
        #pragma unroll
        for (int i = 0; i < 4; i++) {
            int o = (tid + 128 * i) * 16;
            cpa16(sb + S_KV +          o, g_khi + t0 + o);
            cpa16(sb + S_KV +  8192 + o, g_klo + t0 + o);
            cpa16(sb + S_KV + 16384 + o, g_vhi + t0 + o);
            cpa16(sb + S_KV + 24576 + o, g_vlo + t0 + o);
        }
        if (tid < 16) cpa16(sb + S_KK + tid * 16, g_kk + (size_t)bh * N_ + tid * 4);
        cpa_commit();
        cpa_wait0();
    }
    __syncthreads();

    // ---- Q A-fragments (persist in registers) ----
    uint32_t Qh[4][4], Ql[4][4];
    {
        int qrow = wid * 16 + ((mrank & 1) << 3) + l7;
        uint32_t rbase = (uint32_t)qrow * 128;
        uint32_t rx = (uint32_t)((qrow & 7) << 4);
        #pragma unroll
        for (int ks = 0; ks < 4; ks++) {
            uint32_t colb = (uint32_t)(ks * 32 + ((mrank >> 1) << 4));
            uint32_t a = sb + S_QH + rbase + (colb ^ rx);
            ldmx4(Qh[ks], a);
            ldmx4(Ql[ks], a + 8192);
        }
    }
    // all warps must finish reading Q before buf1 (same bytes) is overwritten
    __syncthreads();

    float O[8][4];
    #pragma unroll
    for (int i = 0; i < 8; i++)
        #pragma unroll
        for (int j = 0; j < 4; j++) O[i][j] = 0.f;
    float Lp0 = 0.f, Lp1 = 0.f;

    const int krow16 = ((mrank >> 1) << 3) + l7;
    const int vrow16 = ((mrank & 1) << 3) + l7;
    const uint32_t kcol = (uint32_t)((mrank & 1) << 4);
    const uint32_t vcol = (uint32_t)((mrank >> 1) << 4);

    for (int kt = 0; kt < NT; kt++) {
        const uint32_t cb = sb + S_KV + (uint32_t)(kt & 1) * 32768;

        // prefetch tile kt+1
        if (kt + 1 < NT) {
            const size_t toff = ((size_t)(bh * NT + kt + 1)) << 13;
            const uint32_t dst = sb + S_KV + (uint32_t)((kt + 1) & 1) * 32768;
            #pragma unroll
            for (int i = 0; i < 4; i++) {
                int o = (tid + 128 * i) * 16;
                cpa16(dst +          o, g_khi + toff + o);
                cpa16(dst +  8192 + o, g_klo + toff + o);
                cpa16(dst + 16384 + o, g_vhi + toff + o);
                cpa16(dst + 24576 + o, g_vlo + toff + o);
            }
            if (tid < 16) cpa16(sb + S_KK + ((kt + 1) & 1) * 256 + tid * 16,
                                g_kk + (size_t)bh * N_ + (size_t)(kt + 1) * 64 + tid * 4);
        }
        cpa_commit();
        cpa_wait1();
        __syncthreads();

        // ================ S = Q . K^T (3-term split) ================
        float S[8][4];
        #pragma unroll
        for (int i = 0; i < 8; i++)
            #pragma unroll
            for (int j = 0; j < 4; j++) S[i][j] = 0.f;

        #pragma unroll
        for (int ks = 0; ks < 4; ks++) {
            #pragma unroll
            for (int np = 0; np < 4; np++) {
                int row = np * 16 + krow16;
                uint32_t colb = (uint32_t)(ks * 32) + kcol;
                uint32_t a = cb + (uint32_t)row * 128 + (colb ^ (uint32_t)((row & 7) << 4));
                uint32_t KBh[4], KBl[4];
                ldmx4(KBh, a);
                ldmx4(KBl, a + 8192);
                mma16816(S[2 * np],     Qh[ks], KBh[0], KBh[1]);
                mma16816(S[2 * np + 1], Qh[ks], KBh[2], KBh[3]);
                mma16816(S[2 * np],     Ql[ks], KBh[0], KBh[1]);
                mma16816(S[2 * np + 1], Ql[ks], KBh[2], KBh[3]);
                mma16816(S[2 * np],     Qh[ks], KBl[0], KBl[1]);
                mma16816(S[2 * np + 1], Qh[ks], KBl[2], KBl[3]);
            }
        }

        // ================ softmax numerator -> P A-fragments ================
        const float* kkp = (const float*)(smem + S_KK + (kt & 1) * 256);
        uint32_t Ph[4][4], Pl[4][4];
        #pragma unroll
        for (int nt = 0; nt < 8; nt++) {
            int col = nt * 8 + 2 * (lane & 3);
            float k0 = kkp[col], k1 = kkp[col + 1];
            float p0 = ex2f(fmaf(SCALE_S, S[nt][0], k0));
            float p1 = ex2f(fmaf(SCALE_S, S[nt][1], k1));
            float p2 = ex2f(fmaf(SCALE_S, S[nt][2], k0));
            float p3 = ex2f(fmaf(SCALE_S, S[nt][3], k1));
            Lp0 += p0 + p1;
            Lp1 += p2 + p3;
            uint32_t h01 = pkbf2(p1, p0);
            uint32_t h23 = pkbf2(p3, p2);
            uint32_t l01 = pkbf2(p1 - hi_f32(h01), p0 - lo_f32(h01));
            uint32_t l23 = pkbf2(p3 - hi_f32(h23), p2 - lo_f32(h23));
            Ph[nt >> 1][(nt & 1) * 2]     = h01;
            Ph[nt >> 1][(nt & 1) * 2 + 1] = h23;
            Pl[nt >> 1][(nt & 1) * 2]     = l01;
            Pl[nt >> 1][(nt & 1) * 2 + 1] = l23;
        }

        // ================ O += P . V (3-term split) ================
        #pragma unroll
        for (int j = 0; j < 4; j++) {
            #pragma unroll
            for (int dp = 0; dp < 4; dp++) {
                int row = j * 16 + vrow16;
                uint32_t colb = (uint32_t)(dp * 32) + vcol;
                uint32_t a = cb + 16384 + (uint32_t)row * 128 + (colb ^ (uint32_t)((row & 7) << 4));
                uint32_t VBh[4], VBl[4];
                ldmx4t(VBh, a);
                ldmx4t(VBl, a + 8192);
                mma16816(O[2 * dp],     Ph[j], VBh[0], VBh[1]);
                mma16816(O[2 * dp + 1], Ph[j], VBh[2], VBh[3]);
                mma16816(O[2 * dp],     Pl[j], VBh[0], VBh[1]);
                mma16816(O[2 * dp + 1], Pl[j], VBh[2], VBh[3]);
                mma16816(O[2 * dp],     Ph[j], VBl[0], VBl[1]);
                mma16816(O[2 * dp + 1], Ph[j], VBl[2], VBl[3]);
            }
        }
        __syncthreads();
    }

    // ---- epilogue: reduce row sums across quads, normalize, store ----
    Lp0 += __shfl_xor_sync(0xffffffffu, Lp0, 1);
    Lp0 += __shfl_xor_sync(0xffffffffu, Lp0, 2);
    Lp1 += __shfl_xor_sync(0xffffffffu, Lp1, 1);
    Lp1 += __shfl_xor_sync(0xffffffffu, Lp1, 2);
    float inv0 = 1.0f / Lp0;
    float inv1 = 1.0f / Lp1;

    const int r0 = mt * BM + wid * 16 + (lane >> 2);
    const int dbase = 2 * (lane & 3);
    float* o0 = out + (((size_t)(b * N_ + r0) * H_ + h) << 6);
    float* o1 = out + (((size_t)(b * N_ + r0 + 8) * H_ + h) << 6);
    #pragma unroll
    for (int dt = 0; dt < 8; dt++) {
        int d = dt * 8 + dbase;
        float2 a0 = make_float2(O[dt][0] * inv0, O[dt][1] * inv0);
        float2 a1 = make_float2(O[dt][2] * inv1, O[dt][3] * inv1);
        *(float2*)(o0 + d) = a0;
        *(float2*)(o1 + d) = a1;
    }
}

// ============================ launch ============================
extern "C" void kernel_launch(void* const* d_in, const int* in_sizes, int n_in,
                              void* d_out, int out_size) {
    (void)in_sizes; (void)n_in; (void)out_size;
    const float* q = (const float*)d_in[0];
    const float* k = (const float*)d_in[1];
    const float* v = (const float*)d_in[2];
    float* out = (float*)d_out;

    prep_kernel<<<BH * N_ * 8 / 256, 256>>>(q, k, v);

    cudaFuncSetAttribute(attn_main, cudaFuncAttributeMaxDynamicSharedMemorySize, SMEM_BYTES);
    dim3 grid(MT, BH);
    attn_main<<<grid, 128, SMEM_BYTES>>>(out);
}